// round 12
// baseline (speedup 1.0000x reference)
#include <cuda_runtime.h>
#include <cuda_fp16.h>
#include <cstdint>
#include <math.h>

#define DEV_INLINE __device__ __forceinline__

#define BB 8
#define SS 2048
#define DD 1024
#define MTOT (BB * SS)   // 16384

// ---------------------------------------------------------------------------
// Scratch (__device__ globals; allocation-free rule). 16B aligned for cp.async.
// ---------------------------------------------------------------------------
__device__ __align__(16) __half g_x1h[(size_t)MTOT * DD];
__device__ __align__(16) __half g_x2h[(size_t)MTOT * DD];
__device__ __align__(16) __half g_wqT[DD * DD];
__device__ __align__(16) __half g_wkT[DD * DD];
__device__ __align__(16) __half g_wvT[DD * DD];
__device__ __align__(16) __half g_woT[DD * DD];
__device__ __align__(16) __half g_Q [(size_t)MTOT * DD];
__device__ __align__(16) __half g_K [(size_t)MTOT * DD];
__device__ __align__(16) __half g_Vt[(size_t)DD * MTOT];       // [D, B*S]
__device__ __align__(16) __half g_P [(size_t)BB * SS * SS];
__device__ __align__(16) __half g_Y [(size_t)MTOT * DD];

// ---------------------------------------------------------------------------
// Helpers
// ---------------------------------------------------------------------------
DEV_INLINE uint32_t smem_u32(const void* p) {
    uint32_t a;
    asm("{ .reg .u64 t; cvta.to.shared.u64 t, %1; cvt.u32.u64 %0, t; }" : "=r"(a) : "l"(p));
    return a;
}
DEV_INLINE void cp16(uint32_t s, const void* g) {
    asm volatile("cp.async.cg.shared.global [%0], [%1], 16;" :: "r"(s), "l"(g));
}
DEV_INLINE void cp_commit() { asm volatile("cp.async.commit_group;" ::: "memory"); }
template <int N> DEV_INLINE void cp_wait() {
    asm volatile("cp.async.wait_group %0;" :: "n"(N) : "memory");
}

#define LDSM4(R0, R1, R2, R3, addr)                                           \
    asm volatile("ldmatrix.sync.aligned.m8n8.x4.shared.b16 {%0,%1,%2,%3}, [%4];" \
                 : "=r"(R0), "=r"(R1), "=r"(R2), "=r"(R3) : "r"(addr))

DEV_INLINE void mma_f16(float* d, const uint32_t* a, const uint32_t* b) {
    asm volatile(
        "mma.sync.aligned.m16n8k16.row.col.f32.f16.f16.f32 "
        "{%0,%1,%2,%3}, {%4,%5,%6,%7}, {%8,%9}, {%0,%1,%2,%3};\n"
        : "+f"(d[0]), "+f"(d[1]), "+f"(d[2]), "+f"(d[3])
        : "r"(a[0]), "r"(a[1]), "r"(a[2]), "r"(a[3]),
          "r"(b[0]), "r"(b[1]));
}

// swizzled byte offset of 16B chunk (row, kc) in a k16 sub-tile with 32B rows
DEV_INLINE uint32_t swz(int row, int kc) {
    return (uint32_t)(row * 32 + ((kc ^ ((row >> 2) & 1)) << 4));
}

// ---------------------------------------------------------------------------
// FP16 tensor-core GEMM:  C[M,N] = alpha * A[M,K] @ B[N,K]^T  (K-major fp16)
// CTA tile 128x128, 4 warps (2 M x 2 N), warp tile 64x64.
// Pipeline stage = k32 (two k16 sub-tiles, 16KB), NSTG=4 (64KB/CTA, 2 CTAs/SM),
// 3 stages in flight (96 k-units prefetch, deeper than R10's 80).
// h-loop is `#pragma unroll 1` so only ONE fragment set is live (~190 regs;
// fixes R11's 222-reg interleave). Barriers per CTA halve vs k16 stages.
// MERGE: blockIdx.z selects operand set 0/1. OUTH: store __half; else fp32.
// Grid: (N/128, M/128, z), block 128.
// ---------------------------------------------------------------------------
#define NSTG 4
#define A_BYTES (128 * 32)                  // 4 KB per k16 sub-tile
#define SUB_BYTES (2 * A_BYTES)             // 8 KB  (A + B sub-tile)
#define STG_BYTES (2 * SUB_BYTES)           // 16 KB (k32 stage)
#define SMEM_DYN (NSTG * STG_BYTES)         // 64 KB

template <bool MERGE, bool OUTH, bool RELU>
__global__ void __launch_bounds__(128, 2)
gemm_h(const __half* __restrict__ A0, const __half* __restrict__ B0, void* __restrict__ C0,
       const __half* __restrict__ A1, const __half* __restrict__ B1, void* __restrict__ C1,
       int lda, int ldb, int ldc, int nk2, float alpha0, float alpha1,
       size_t sAz, size_t sBz, size_t sCz)
{
    const bool sel = MERGE && (blockIdx.z & 1);
    const __half* A = sel ? A1 : A0;
    const __half* B = sel ? B1 : B0;
    void* Cv        = sel ? C1 : C0;
    const float alpha = sel ? alpha1 : alpha0;
    const size_t zoff = MERGE ? 0 : (size_t)blockIdx.z;
    A += zoff * sAz;
    B += zoff * sBz;

    const int bm = blockIdx.y, bn = blockIdx.x;
    const int tid  = threadIdx.x;
    const int warp = tid >> 5;
    const int lane = tid & 31;
    const int wm   = warp >> 1;             // 0..1 : 64-row band
    const int wn   = warp & 1;              // 0..1 : 64-col band
    const int grp  = lane >> 2;             // 0..7
    const int tig  = lane & 3;              // 0..3

    extern __shared__ char dsm[];
    const uint32_t sb = smem_u32(dsm);

    // per-lane ldmatrix.x4 offsets within a k16 sub-tile (verified mapping)
    const int lT = lane >> 3, lr = lane & 7;
    uint32_t offA[4], offB[4];
    {
        const int am  = wm * 64 + (lT & 1) * 8 + lr;     // + mt*16
        const int akc = lT >> 1;
#pragma unroll
        for (int mt = 0; mt < 4; mt++) offA[mt] = swz(am + mt * 16, akc);
        const int bn0 = wn * 64 + ((lT >> 1) << 3) + lr; // + j*16
        const int bkc = lT & 1;
#pragma unroll
        for (int j = 0; j < 4; j++) offB[j] = (uint32_t)A_BYTES + swz(bn0 + j * 16, bkc);
    }

    const __half* Abase = A + (size_t)(bm * 128) * lda;
    const __half* Bbase = B + (size_t)(bn * 128) * ldb;

    // load one k32 stage (two k16 sub-tiles), one commit group
    auto load_stage = [&](int s, int kt2) {
        const uint32_t stg = sb + (uint32_t)(s * STG_BYTES);
#pragma unroll
        for (int h = 0; h < 2; h++) {
            const uint32_t st = stg + (uint32_t)(h * SUB_BYTES);
            const int k0 = kt2 * 32 + h * 16;
#pragma unroll
            for (int i = 0; i < 2; i++) {    // A: 128 rows x 2 chunks
                const int lin = tid + i * 128;
                const int row = lin >> 1, kc = lin & 1;
                cp16(st + swz(row, kc), Abase + (size_t)row * lda + k0 + kc * 8);
            }
#pragma unroll
            for (int i = 0; i < 2; i++) {    // B: 128 rows x 2 chunks
                const int lin = tid + i * 128;
                const int row = lin >> 1, kc = lin & 1;
                cp16(st + A_BYTES + swz(row, kc), Bbase + (size_t)row * ldb + k0 + kc * 8);
            }
        }
        cp_commit();
    };

    // prologue: stages 0..2 in flight
    load_stage(0, 0);
    load_stage(1, 1);
    load_stage(2, 2);

    float acc[4][8][4] = {};

    for (int kt2 = 0; kt2 < nk2; kt2++) {
        const int rem = nk2 - 1 - kt2;
        if      (rem >= 2) cp_wait<2>();
        else if (rem == 1) cp_wait<1>();
        else               cp_wait<0>();
        __syncthreads();

        if (kt2 + 3 < nk2) load_stage((kt2 + 3) & 3, kt2 + 3);

        const uint32_t stg = sb + (uint32_t)((kt2 & 3) * STG_BYTES);

#pragma unroll 1
        for (int h = 0; h < 2; h++) {
            const uint32_t st = stg + (uint32_t)(h * SUB_BYTES);
            uint32_t a[4][4], b[8][2];
#pragma unroll
            for (int mt = 0; mt < 4; mt++)
                LDSM4(a[mt][0], a[mt][1], a[mt][2], a[mt][3], st + offA[mt]);
#pragma unroll
            for (int j = 0; j < 4; j++) {
                uint32_t r0, r1, r2, r3;
                LDSM4(r0, r1, r2, r3, st + offB[j]);
                b[2 * j][0] = r0; b[2 * j][1] = r1;
                b[2 * j + 1][0] = r2; b[2 * j + 1][1] = r3;
            }
#pragma unroll
            for (int mt = 0; mt < 4; mt++)
#pragma unroll
                for (int nt = 0; nt < 8; nt++)
                    mma_f16(acc[mt][nt], a[mt], b[nt]);
        }
    }

    // ---- epilogue ----
    const int r0 = bm * 128 + wm * 64;
    const int c0 = bn * 128 + wn * 64;
#pragma unroll
    for (int mt = 0; mt < 4; mt++) {
#pragma unroll
        for (int nt = 0; nt < 8; nt++) {
            const int r = r0 + mt * 16 + grp;
            const int c = c0 + nt * 8 + tig * 2;
            float v0 = acc[mt][nt][0] * alpha;
            float v1 = acc[mt][nt][1] * alpha;
            float v2 = acc[mt][nt][2] * alpha;
            float v3 = acc[mt][nt][3] * alpha;
            if (RELU) {
                v0 = fmaxf(v0, 0.f); v1 = fmaxf(v1, 0.f);
                v2 = fmaxf(v2, 0.f); v3 = fmaxf(v3, 0.f);
            }
            if (OUTH) {
                __half* C = (__half*)Cv + zoff * sCz;
                *(__half2*)(C + (size_t)r * ldc + c)       = __floats2half2_rn(v0, v1);
                *(__half2*)(C + (size_t)(r + 8) * ldc + c) = __floats2half2_rn(v2, v3);
            } else {
                float* C = (float*)Cv + zoff * sCz;
                *(float2*)(C + (size_t)r * ldc + c)       = make_float2(v0, v1);
                *(float2*)(C + (size_t)(r + 8) * ldc + c) = make_float2(v2, v3);
            }
        }
    }
}

// ---------------------------------------------------------------------------
// Prep: fp32 -> fp16 for x1 and x2 in one launch (blockIdx.y selects)
// ---------------------------------------------------------------------------
__global__ void __launch_bounds__(256)
f2h_two(const float4* __restrict__ s1, __half2* __restrict__ d1,
        const float4* __restrict__ s2, __half2* __restrict__ d2, int n4)
{
    const int i = blockIdx.x * 256 + threadIdx.x;
    if (i >= n4) return;
    const float4* s = blockIdx.y ? s2 : s1;
    __half2*      d = blockIdx.y ? d2 : d1;
    const float4 v = s[i];
    d[2 * i]     = __floats2half2_rn(v.x, v.y);
    d[2 * i + 1] = __floats2half2_rn(v.z, v.w);
}

// 4 weight transposes (to K-major) + fp16 convert in one launch (blockIdx.z)
__global__ void __launch_bounds__(256)
transpose_h4(const float* __restrict__ w0, const float* __restrict__ w1,
             const float* __restrict__ w2, const float* __restrict__ w3,
             __half* __restrict__ t0, __half* __restrict__ t1,
             __half* __restrict__ t2, __half* __restrict__ t3)
{
    const float* w = (blockIdx.z == 0) ? w0 : (blockIdx.z == 1) ? w1
                   : (blockIdx.z == 2) ? w2 : w3;
    __half* wt     = (blockIdx.z == 0) ? t0 : (blockIdx.z == 1) ? t1
                   : (blockIdx.z == 2) ? t2 : t3;

    __shared__ float t[32][33];
    const int bx = blockIdx.x * 32, by = blockIdx.y * 32;
    const int x = threadIdx.x & 31, y4 = threadIdx.x >> 5;
#pragma unroll
    for (int i = 0; i < 32; i += 8)
        t[y4 + i][x] = w[(size_t)(by + y4 + i) * DD + bx + x];
    __syncthreads();
#pragma unroll
    for (int i = 0; i < 32; i += 8)
        wt[(size_t)(bx + y4 + i) * DD + by + x] = __float2half_rn(t[x][y4 + i]);
}

// ---------------------------------------------------------------------------
// Row softmax with additive mask on fp16 P (compute fp32, store fp16)
// ---------------------------------------------------------------------------
__global__ void __launch_bounds__(256)
softmax_mask(__half* __restrict__ P, const int* __restrict__ mask)
{
    const int row = blockIdx.x;
    const int b   = row >> 11;
    __half* p = P + (size_t)row * SS;
    const int* mrow = mask + (size_t)b * SS;

    const int tid = threadIdx.x, lane = tid & 31, warp = tid >> 5;
    __shared__ float red[8];

    float v[8];
    float mx = -INFINITY;
#pragma unroll
    for (int i = 0; i < 8; i++) {
        const int j = tid + i * 256;
        float x = __half2float(p[j]);
        if (mrow[j]) x -= 1.0e9f;
        v[i] = x;
        mx = fmaxf(mx, x);
    }
#pragma unroll
    for (int o = 16; o; o >>= 1) mx = fmaxf(mx, __shfl_xor_sync(0xffffffffu, mx, o));
    if (lane == 0) red[warp] = mx;
    __syncthreads();
    mx = red[0];
#pragma unroll
    for (int w = 1; w < 8; w++) mx = fmaxf(mx, red[w]);

    float s = 0.f;
#pragma unroll
    for (int i = 0; i < 8; i++) {
        const float e = __expf(v[i] - mx);
        v[i] = e;
        s += e;
    }
    __syncthreads();
#pragma unroll
    for (int o = 16; o; o >>= 1) s += __shfl_xor_sync(0xffffffffu, s, o);
    if (lane == 0) red[warp] = s;
    __syncthreads();
    s = red[0];
#pragma unroll
    for (int w = 1; w < 8; w++) s += red[w];

    const float inv = 1.0f / s;
#pragma unroll
    for (int i = 0; i < 8; i++) p[tid + i * 256] = __float2half_rn(v[i] * inv);
}

// ---------------------------------------------------------------------------
// Launch
// ---------------------------------------------------------------------------
extern "C" void kernel_launch(void* const* d_in, const int* in_sizes, int n_in,
                              void* d_out, int out_size)
{
    (void)in_sizes; (void)n_in; (void)out_size;

    const float* x1      = (const float*)d_in[0];
    const float* x2      = (const float*)d_in[1];
    const int*   maskSeq = (const int*)  d_in[2];
    const float* wq      = (const float*)d_in[3];
    const float* wk      = (const float*)d_in[4];
    const float* wv      = (const float*)d_in[5];
    const float* wo      = (const float*)d_in[6];
    float* out = (float*)d_out;

    __half *x1h, *x2h, *wqT, *wkT, *wvT, *woT, *Q, *Kp, *Vt, *P, *Y;
    cudaGetSymbolAddress((void**)&x1h, g_x1h);
    cudaGetSymbolAddress((void**)&x2h, g_x2h);
    cudaGetSymbolAddress((void**)&wqT, g_wqT);
    cudaGetSymbolAddress((void**)&wkT, g_wkT);
    cudaGetSymbolAddress((void**)&wvT, g_wvT);
    cudaGetSymbolAddress((void**)&woT, g_woT);
    cudaGetSymbolAddress((void**)&Q,   g_Q);
    cudaGetSymbolAddress((void**)&Kp,  g_K);
    cudaGetSymbolAddress((void**)&Vt,  g_Vt);
    cudaGetSymbolAddress((void**)&P,   g_P);
    cudaGetSymbolAddress((void**)&Y,   g_Y);

    cudaFuncSetAttribute(gemm_h<true,  true,  false>, cudaFuncAttributeMaxDynamicSharedMemorySize, SMEM_DYN);
    cudaFuncSetAttribute(gemm_h<false, true,  false>, cudaFuncAttributeMaxDynamicSharedMemorySize, SMEM_DYN);
    cudaFuncSetAttribute(gemm_h<false, true,  true >, cudaFuncAttributeMaxDynamicSharedMemorySize, SMEM_DYN);
    cudaFuncSetAttribute(gemm_h<false, false, false>, cudaFuncAttributeMaxDynamicSharedMemorySize, SMEM_DYN);

    const float scale = 0.03125f;   // 1024^-0.5
    const int n4 = (MTOT * DD) / 4;

    // prep (2 launches)
    f2h_two<<<dim3(n4 / 256, 2), 256>>>((const float4*)x1, (__half2*)x1h,
                                        (const float4*)x2, (__half2*)x2h, n4);
    transpose_h4<<<dim3(32, 32, 4), 256>>>(wq, wk, wv, wo, wqT, wkT, wvT, woT);

    // merged: Q = h(scale * x1 @ wq)  and  K = h(x2 @ wk)
    gemm_h<true, true, false><<<dim3(DD / 128, MTOT / 128, 2), 128, SMEM_DYN>>>(
        x1h, wqT, Q, x2h, wkT, Kp, DD, DD, DD, DD / 32, scale, 1.f, 0, 0, 0);

    // Vt[e, s] = h( sum_d wvT[e,d] * x2h[s,d] )   (V transposed, K-major for PV)
    gemm_h<false, true, false><<<dim3(MTOT / 128, DD / 128, 1), 128, SMEM_DYN>>>(
        wvT, x2h, Vt, wvT, x2h, Vt, DD, DD, MTOT, DD / 32, 1.f, 1.f, 0, 0, 0);

    // P = Q @ K^T  (per batch)
    gemm_h<false, true, false><<<dim3(SS / 128, SS / 128, BB), 128, SMEM_DYN>>>(
        Q, Kp, P, Q, Kp, P, DD, DD, SS, DD / 32, 1.f, 1.f,
        (size_t)SS * DD, (size_t)SS * DD, (size_t)SS * SS);

    // mask + softmax (in place, fp16)
    softmax_mask<<<BB * SS, 256>>>(P, maskSeq);

    // Y = h(relu(P @ Vt^T))  (per batch; Vt batch slice via column offset)
    gemm_h<false, true, true><<<dim3(DD / 128, SS / 128, BB), 128, SMEM_DYN>>>(
        P, Vt, Y, P, Vt, Y, SS, MTOT, DD, SS / 32, 1.f, 1.f,
        (size_t)SS * SS, (size_t)SS, (size_t)SS * DD);

    // out = Y @ wo (fp32 out)
    gemm_h<false, false, false><<<dim3(DD / 128, MTOT / 128, 1), 128, SMEM_DYN>>>(
        Y, woT, out, Y, woT, out, DD, DD, DD, DD / 32, 1.f, 1.f, 0, 0, 0);
}

// round 14
// speedup vs baseline: 1.2271x; 1.2271x over previous
#include <cuda_runtime.h>
#include <cuda_fp16.h>
#include <cstdint>
#include <math.h>

#define DEV_INLINE __device__ __forceinline__

#define BB 8
#define SS 2048
#define DD 1024
#define MTOT (BB * SS)   // 16384

// ---------------------------------------------------------------------------
// Scratch (__device__ globals; allocation-free rule). 16B aligned for cp.async.
// ---------------------------------------------------------------------------
__device__ __align__(16) __half g_x1h[(size_t)MTOT * DD];
__device__ __align__(16) __half g_x2h[(size_t)MTOT * DD];
__device__ __align__(16) __half g_wqT[DD * DD];
__device__ __align__(16) __half g_wkT[DD * DD];
__device__ __align__(16) __half g_wvT[DD * DD];
__device__ __align__(16) __half g_woT[DD * DD];
__device__ __align__(16) __half g_Q [(size_t)MTOT * DD];
__device__ __align__(16) __half g_K [(size_t)MTOT * DD];
__device__ __align__(16) __half g_Vt[(size_t)DD * MTOT];       // [D, B*S]
__device__ __align__(16) __half g_P [(size_t)BB * SS * SS];
__device__ __align__(16) __half g_Y [(size_t)MTOT * DD];

// ---------------------------------------------------------------------------
// Helpers
// ---------------------------------------------------------------------------
DEV_INLINE uint32_t smem_u32(const void* p) {
    uint32_t a;
    asm("{ .reg .u64 t; cvta.to.shared.u64 t, %1; cvt.u32.u64 %0, t; }" : "=r"(a) : "l"(p));
    return a;
}
DEV_INLINE void cp16(uint32_t s, const void* g) {
    asm volatile("cp.async.cg.shared.global [%0], [%1], 16;" :: "r"(s), "l"(g));
}
DEV_INLINE void cp_commit() { asm volatile("cp.async.commit_group;" ::: "memory"); }
template <int N> DEV_INLINE void cp_wait() {
    asm volatile("cp.async.wait_group %0;" :: "n"(N) : "memory");
}

#define LDSM4(R0, R1, R2, R3, addr)                                           \
    asm volatile("ldmatrix.sync.aligned.m8n8.x4.shared.b16 {%0,%1,%2,%3}, [%4];" \
                 : "=r"(R0), "=r"(R1), "=r"(R2), "=r"(R3) : "r"(addr))

DEV_INLINE void mma_f16(float* d, const uint32_t* a, const uint32_t* b) {
    asm volatile(
        "mma.sync.aligned.m16n8k16.row.col.f32.f16.f16.f32 "
        "{%0,%1,%2,%3}, {%4,%5,%6,%7}, {%8,%9}, {%0,%1,%2,%3};\n"
        : "+f"(d[0]), "+f"(d[1]), "+f"(d[2]), "+f"(d[3])
        : "r"(a[0]), "r"(a[1]), "r"(a[2]), "r"(a[3]),
          "r"(b[0]), "r"(b[1]));
}

// swizzled byte offset of 16B chunk (row, kc) in a k16 sub-tile with 32B rows
DEV_INLINE uint32_t swz(int row, int kc) {
    return (uint32_t)(row * 32 + ((kc ^ ((row >> 2) & 1)) << 4));
}

// ---------------------------------------------------------------------------
// FP16 tensor-core GEMM:  C[M,N] = alpha * A[M,K] @ B[N,K]^T  (K-major fp16)
// CTA tile 128x128, 4 warps (2 M x 2 N), warp tile 64x64.
// Pipeline stage = k32 (two k16 sub-tiles, 16KB), NSTG=4 (64KB/CTA, 2 CTAs/SM),
// 3 stages in flight (96 k-units of prefetch, deeper than R10's 80).
// h-loop FULLY unrolled: ptxas hoists LDSM(h1) under the HMMA(h0) burst
// (intra-stage fragment double-buffer, ~222 regs — still 2 CTAs/SM).
// Barriers per CTA halve vs k16 stages (160 vs 320 sync events).
// MERGE: blockIdx.z selects operand set 0/1. OUTH: store __half; else fp32.
// Grid: (N/128, M/128, z), block 128.
// ---------------------------------------------------------------------------
#define NSTG 4
#define A_BYTES (128 * 32)                  // 4 KB per k16 sub-tile
#define SUB_BYTES (2 * A_BYTES)             // 8 KB  (A + B sub-tile)
#define STG_BYTES (2 * SUB_BYTES)           // 16 KB (k32 stage)
#define SMEM_DYN (NSTG * STG_BYTES)         // 64 KB

template <bool MERGE, bool OUTH, bool RELU>
__global__ void __launch_bounds__(128, 2)
gemm_h(const __half* __restrict__ A0, const __half* __restrict__ B0, void* __restrict__ C0,
       const __half* __restrict__ A1, const __half* __restrict__ B1, void* __restrict__ C1,
       int lda, int ldb, int ldc, int nk2, float alpha0, float alpha1,
       size_t sAz, size_t sBz, size_t sCz)
{
    const bool sel = MERGE && (blockIdx.z & 1);
    const __half* A = sel ? A1 : A0;
    const __half* B = sel ? B1 : B0;
    void* Cv        = sel ? C1 : C0;
    const float alpha = sel ? alpha1 : alpha0;
    const size_t zoff = MERGE ? 0 : (size_t)blockIdx.z;
    A += zoff * sAz;
    B += zoff * sBz;

    const int bm = blockIdx.y, bn = blockIdx.x;
    const int tid  = threadIdx.x;
    const int warp = tid >> 5;
    const int lane = tid & 31;
    const int wm   = warp >> 1;             // 0..1 : 64-row band
    const int wn   = warp & 1;              // 0..1 : 64-col band
    const int grp  = lane >> 2;             // 0..7
    const int tig  = lane & 3;              // 0..3

    extern __shared__ char dsm[];
    const uint32_t sb = smem_u32(dsm);

    // per-lane ldmatrix.x4 offsets within a k16 sub-tile (verified mapping)
    const int lT = lane >> 3, lr = lane & 7;
    uint32_t offA[4], offB[4];
    {
        const int am  = wm * 64 + (lT & 1) * 8 + lr;     // + mt*16
        const int akc = lT >> 1;
#pragma unroll
        for (int mt = 0; mt < 4; mt++) offA[mt] = swz(am + mt * 16, akc);
        const int bn0 = wn * 64 + ((lT >> 1) << 3) + lr; // + j*16
        const int bkc = lT & 1;
#pragma unroll
        for (int j = 0; j < 4; j++) offB[j] = (uint32_t)A_BYTES + swz(bn0 + j * 16, bkc);
    }

    const __half* Abase = A + (size_t)(bm * 128) * lda;
    const __half* Bbase = B + (size_t)(bn * 128) * ldb;

    // load one k32 stage (two k16 sub-tiles), one commit group
    auto load_stage = [&](int s, int kt2) {
        const uint32_t stg = sb + (uint32_t)(s * STG_BYTES);
#pragma unroll
        for (int h = 0; h < 2; h++) {
            const uint32_t st = stg + (uint32_t)(h * SUB_BYTES);
            const int k0 = kt2 * 32 + h * 16;
#pragma unroll
            for (int i = 0; i < 2; i++) {    // A: 128 rows x 2 chunks
                const int lin = tid + i * 128;
                const int row = lin >> 1, kc = lin & 1;
                cp16(st + swz(row, kc), Abase + (size_t)row * lda + k0 + kc * 8);
            }
#pragma unroll
            for (int i = 0; i < 2; i++) {    // B: 128 rows x 2 chunks
                const int lin = tid + i * 128;
                const int row = lin >> 1, kc = lin & 1;
                cp16(st + A_BYTES + swz(row, kc), Bbase + (size_t)row * ldb + k0 + kc * 8);
            }
        }
        cp_commit();
    };

    // prologue: stages 0..2 in flight
    load_stage(0, 0);
    load_stage(1, 1);
    load_stage(2, 2);

    float acc[4][8][4] = {};

    for (int kt2 = 0; kt2 < nk2; kt2++) {
        const int rem = nk2 - 1 - kt2;
        if      (rem >= 2) cp_wait<2>();
        else if (rem == 1) cp_wait<1>();
        else               cp_wait<0>();
        __syncthreads();

        if (kt2 + 3 < nk2) load_stage((kt2 + 3) & 3, kt2 + 3);

        const uint32_t stg = sb + (uint32_t)((kt2 & 3) * STG_BYTES);

#pragma unroll
        for (int h = 0; h < 2; h++) {
            const uint32_t st = stg + (uint32_t)(h * SUB_BYTES);
            uint32_t a[4][4], b[8][2];
#pragma unroll
            for (int mt = 0; mt < 4; mt++)
                LDSM4(a[mt][0], a[mt][1], a[mt][2], a[mt][3], st + offA[mt]);
#pragma unroll
            for (int j = 0; j < 4; j++) {
                uint32_t r0, r1, r2, r3;
                LDSM4(r0, r1, r2, r3, st + offB[j]);
                b[2 * j][0] = r0; b[2 * j][1] = r1;
                b[2 * j + 1][0] = r2; b[2 * j + 1][1] = r3;
            }
#pragma unroll
            for (int mt = 0; mt < 4; mt++)
#pragma unroll
                for (int nt = 0; nt < 8; nt++)
                    mma_f16(acc[mt][nt], a[mt], b[nt]);
        }
    }

    // ---- epilogue ----
    const int r0 = bm * 128 + wm * 64;
    const int c0 = bn * 128 + wn * 64;
#pragma unroll
    for (int mt = 0; mt < 4; mt++) {
#pragma unroll
        for (int nt = 0; nt < 8; nt++) {
            const int r = r0 + mt * 16 + grp;
            const int c = c0 + nt * 8 + tig * 2;
            float v0 = acc[mt][nt][0] * alpha;
            float v1 = acc[mt][nt][1] * alpha;
            float v2 = acc[mt][nt][2] * alpha;
            float v3 = acc[mt][nt][3] * alpha;
            if (RELU) {
                v0 = fmaxf(v0, 0.f); v1 = fmaxf(v1, 0.f);
                v2 = fmaxf(v2, 0.f); v3 = fmaxf(v3, 0.f);
            }
            if (OUTH) {
                __half* C = (__half*)Cv + zoff * sCz;
                *(__half2*)(C + (size_t)r * ldc + c)       = __floats2half2_rn(v0, v1);
                *(__half2*)(C + (size_t)(r + 8) * ldc + c) = __floats2half2_rn(v2, v3);
            } else {
                float* C = (float*)Cv + zoff * sCz;
                *(float2*)(C + (size_t)r * ldc + c)       = make_float2(v0, v1);
                *(float2*)(C + (size_t)(r + 8) * ldc + c) = make_float2(v2, v3);
            }
        }
    }
}

// ---------------------------------------------------------------------------
// Prep: fp32 -> fp16 for x1 and x2 in one launch (blockIdx.y selects)
// ---------------------------------------------------------------------------
__global__ void __launch_bounds__(256)
f2h_two(const float4* __restrict__ s1, __half2* __restrict__ d1,
        const float4* __restrict__ s2, __half2* __restrict__ d2, int n4)
{
    const int i = blockIdx.x * 256 + threadIdx.x;
    if (i >= n4) return;
    const float4* s = blockIdx.y ? s2 : s1;
    __half2*      d = blockIdx.y ? d2 : d1;
    const float4 v = s[i];
    d[2 * i]     = __floats2half2_rn(v.x, v.y);
    d[2 * i + 1] = __floats2half2_rn(v.z, v.w);
}

// 4 weight transposes (to K-major) + fp16 convert in one launch (blockIdx.z)
__global__ void __launch_bounds__(256)
transpose_h4(const float* __restrict__ w0, const float* __restrict__ w1,
             const float* __restrict__ w2, const float* __restrict__ w3,
             __half* __restrict__ t0, __half* __restrict__ t1,
             __half* __restrict__ t2, __half* __restrict__ t3)
{
    const float* w = (blockIdx.z == 0) ? w0 : (blockIdx.z == 1) ? w1
                   : (blockIdx.z == 2) ? w2 : w3;
    __half* wt     = (blockIdx.z == 0) ? t0 : (blockIdx.z == 1) ? t1
                   : (blockIdx.z == 2) ? t2 : t3;

    __shared__ float t[32][33];
    const int bx = blockIdx.x * 32, by = blockIdx.y * 32;
    const int x = threadIdx.x & 31, y4 = threadIdx.x >> 5;
#pragma unroll
    for (int i = 0; i < 32; i += 8)
        t[y4 + i][x] = w[(size_t)(by + y4 + i) * DD + bx + x];
    __syncthreads();
#pragma unroll
    for (int i = 0; i < 32; i += 8)
        wt[(size_t)(bx + y4 + i) * DD + by + x] = __float2half_rn(t[x][y4 + i]);
}

// ---------------------------------------------------------------------------
// Row softmax with additive mask on fp16 P (compute fp32, store fp16)
// ---------------------------------------------------------------------------
__global__ void __launch_bounds__(256)
softmax_mask(__half* __restrict__ P, const int* __restrict__ mask)
{
    const int row = blockIdx.x;
    const int b   = row >> 11;
    __half* p = P + (size_t)row * SS;
    const int* mrow = mask + (size_t)b * SS;

    const int tid = threadIdx.x, lane = tid & 31, warp = tid >> 5;
    __shared__ float red[8];

    float v[8];
    float mx = -INFINITY;
#pragma unroll
    for (int i = 0; i < 8; i++) {
        const int j = tid + i * 256;
        float x = __half2float(p[j]);
        if (mrow[j]) x -= 1.0e9f;
        v[i] = x;
        mx = fmaxf(mx, x);
    }
#pragma unroll
    for (int o = 16; o; o >>= 1) mx = fmaxf(mx, __shfl_xor_sync(0xffffffffu, mx, o));
    if (lane == 0) red[warp] = mx;
    __syncthreads();
    mx = red[0];
#pragma unroll
    for (int w = 1; w < 8; w++) mx = fmaxf(mx, red[w]);

    float s = 0.f;
#pragma unroll
    for (int i = 0; i < 8; i++) {
        const float e = __expf(v[i] - mx);
        v[i] = e;
        s += e;
    }
    __syncthreads();
#pragma unroll
    for (int o = 16; o; o >>= 1) s += __shfl_xor_sync(0xffffffffu, s, o);
    if (lane == 0) red[warp] = s;
    __syncthreads();
    s = red[0];
#pragma unroll
    for (int w = 1; w < 8; w++) s += red[w];

    const float inv = 1.0f / s;
#pragma unroll
    for (int i = 0; i < 8; i++) p[tid + i * 256] = __float2half_rn(v[i] * inv);
}

// ---------------------------------------------------------------------------
// Launch
// ---------------------------------------------------------------------------
extern "C" void kernel_launch(void* const* d_in, const int* in_sizes, int n_in,
                              void* d_out, int out_size)
{
    (void)in_sizes; (void)n_in; (void)out_size;

    const float* x1      = (const float*)d_in[0];
    const float* x2      = (const float*)d_in[1];
    const int*   maskSeq = (const int*)  d_in[2];
    const float* wq      = (const float*)d_in[3];
    const float* wk      = (const float*)d_in[4];
    const float* wv      = (const float*)d_in[5];
    const float* wo      = (const float*)d_in[6];
    float* out = (float*)d_out;

    __half *x1h, *x2h, *wqT, *wkT, *wvT, *woT, *Q, *Kp, *Vt, *P, *Y;
    cudaGetSymbolAddress((void**)&x1h, g_x1h);
    cudaGetSymbolAddress((void**)&x2h, g_x2h);
    cudaGetSymbolAddress((void**)&wqT, g_wqT);
    cudaGetSymbolAddress((void**)&wkT, g_wkT);
    cudaGetSymbolAddress((void**)&wvT, g_wvT);
    cudaGetSymbolAddress((void**)&woT, g_woT);
    cudaGetSymbolAddress((void**)&Q,   g_Q);
    cudaGetSymbolAddress((void**)&Kp,  g_K);
    cudaGetSymbolAddress((void**)&Vt,  g_Vt);
    cudaGetSymbolAddress((void**)&P,   g_P);
    cudaGetSymbolAddress((void**)&Y,   g_Y);

    cudaFuncSetAttribute(gemm_h<true,  true,  false>, cudaFuncAttributeMaxDynamicSharedMemorySize, SMEM_DYN);
    cudaFuncSetAttribute(gemm_h<false, true,  false>, cudaFuncAttributeMaxDynamicSharedMemorySize, SMEM_DYN);
    cudaFuncSetAttribute(gemm_h<false, true,  true >, cudaFuncAttributeMaxDynamicSharedMemorySize, SMEM_DYN);
    cudaFuncSetAttribute(gemm_h<false, false, false>, cudaFuncAttributeMaxDynamicSharedMemorySize, SMEM_DYN);

    const float scale = 0.03125f;   // 1024^-0.5
    const int n4 = (MTOT * DD) / 4;

    // prep (2 launches)
    f2h_two<<<dim3(n4 / 256, 2), 256>>>((const float4*)x1, (__half2*)x1h,
                                        (const float4*)x2, (__half2*)x2h, n4);
    transpose_h4<<<dim3(32, 32, 4), 256>>>(wq, wk, wv, wo, wqT, wkT, wvT, woT);

    // merged: Q = h(scale * x1 @ wq)  and  K = h(x2 @ wk)
    gemm_h<true, true, false><<<dim3(DD / 128, MTOT / 128, 2), 128, SMEM_DYN>>>(
        x1h, wqT, Q, x2h, wkT, Kp, DD, DD, DD, DD / 32, scale, 1.f, 0, 0, 0);

    // Vt[e, s] = h( sum_d wvT[e,d] * x2h[s,d] )   (V transposed, K-major for PV)
    gemm_h<false, true, false><<<dim3(MTOT / 128, DD / 128, 1), 128, SMEM_DYN>>>(
        wvT, x2h, Vt, wvT, x2h, Vt, DD, DD, MTOT, DD / 32, 1.f, 1.f, 0, 0, 0);

    // P = Q @ K^T  (per batch)
    gemm_h<false, true, false><<<dim3(SS / 128, SS / 128, BB), 128, SMEM_DYN>>>(
        Q, Kp, P, Q, Kp, P, DD, DD, SS, DD / 32, 1.f, 1.f,
        (size_t)SS * DD, (size_t)SS * DD, (size_t)SS * SS);

    // mask + softmax (in place, fp16)
    softmax_mask<<<BB * SS, 256>>>(P, maskSeq);

    // Y = h(relu(P @ Vt^T))  (per batch; Vt batch slice via column offset)
    gemm_h<false, true, true><<<dim3(DD / 128, SS / 128, BB), 128, SMEM_DYN>>>(
        P, Vt, Y, P, Vt, Y, SS, MTOT, DD, SS / 32, 1.f, 1.f,
        (size_t)SS * SS, (size_t)SS, (size_t)SS * DD);

    // out = Y @ wo (fp32 out)
    gemm_h<false, false, false><<<dim3(DD / 128, MTOT / 128, 1), 128, SMEM_DYN>>>(
        Y, woT, out, Y, woT, out, DD, DD, DD, DD / 32, 1.f, 1.f, 0, 0, 0);
}

// round 15
// speedup vs baseline: 1.2499x; 1.0186x over previous
#include <cuda_runtime.h>
#include <cuda_fp16.h>
#include <cstdint>
#include <math.h>

#define DEV_INLINE __device__ __forceinline__

#define BB 8
#define SS 2048
#define DD 1024
#define MTOT (BB * SS)   // 16384

// ---------------------------------------------------------------------------
// Scratch (__device__ globals; allocation-free rule). 16B aligned for cp.async.
// ---------------------------------------------------------------------------
__device__ __align__(16) __half g_x1h[(size_t)MTOT * DD];
__device__ __align__(16) __half g_x2h[(size_t)MTOT * DD];
__device__ __align__(16) __half g_wqT[DD * DD];
__device__ __align__(16) __half g_wkT[DD * DD];
__device__ __align__(16) __half g_wvT[DD * DD];
__device__ __align__(16) __half g_woT[DD * DD];
__device__ __align__(16) __half g_Q [(size_t)MTOT * DD];
__device__ __align__(16) __half g_K [(size_t)MTOT * DD];
__device__ __align__(16) __half g_Vt[(size_t)DD * MTOT];       // [D, B*S]
__device__ __align__(16) __half g_P [(size_t)BB * SS * SS];
__device__ __align__(16) __half g_Y [(size_t)MTOT * DD];

// ---------------------------------------------------------------------------
// Helpers
// ---------------------------------------------------------------------------
DEV_INLINE uint32_t smem_u32(const void* p) {
    uint32_t a;
    asm("{ .reg .u64 t; cvta.to.shared.u64 t, %1; cvt.u32.u64 %0, t; }" : "=r"(a) : "l"(p));
    return a;
}
DEV_INLINE void cp16(uint32_t s, const void* g) {
    asm volatile("cp.async.cg.shared.global [%0], [%1], 16;" :: "r"(s), "l"(g));
}
DEV_INLINE void cp_commit() { asm volatile("cp.async.commit_group;" ::: "memory"); }
template <int N> DEV_INLINE void cp_wait() {
    asm volatile("cp.async.wait_group %0;" :: "n"(N) : "memory");
}

#define LDSM4(R0, R1, R2, R3, addr)                                           \
    asm volatile("ldmatrix.sync.aligned.m8n8.x4.shared.b16 {%0,%1,%2,%3}, [%4];" \
                 : "=r"(R0), "=r"(R1), "=r"(R2), "=r"(R3) : "r"(addr))

DEV_INLINE void mma_f16(float* d, const uint32_t* a, const uint32_t* b) {
    asm volatile(
        "mma.sync.aligned.m16n8k16.row.col.f32.f16.f16.f32 "
        "{%0,%1,%2,%3}, {%4,%5,%6,%7}, {%8,%9}, {%0,%1,%2,%3};\n"
        : "+f"(d[0]), "+f"(d[1]), "+f"(d[2]), "+f"(d[3])
        : "r"(a[0]), "r"(a[1]), "r"(a[2]), "r"(a[3]),
          "r"(b[0]), "r"(b[1]));
}

// swizzled byte offset of 16B chunk (row, kc) in a k16 tile with 32B rows
DEV_INLINE uint32_t swz(int row, int kc) {
    return (uint32_t)(row * 32 + ((kc ^ ((row >> 2) & 1)) << 4));
}

// ---------------------------------------------------------------------------
// FP16 tensor-core GEMM:  C[M,N] = alpha * A[M,K] @ B[N,K]^T  (K-major fp16)
// CTA tile 128x128, 4 warps (2 M x 2 N), warp tile 64x64, k-step 16.
// 8-stage cp.async pipeline (64KB/CTA, 2 CTAs/SM, 112 k-units prefetch).
// Loop order: LDSM fragments FIRST, then issue next-stage cp.async refill —
// fragments don't queue behind fill on the LSU port, HMMAs start earlier,
// and the refill drains under the HMMA burst.
// Single-buffered fragments (~190 regs, spill-free R10 body).
// MERGE: blockIdx.z selects operand set 0/1. OUTH: store __half; else fp32.
// Grid: (N/128, M/128, z), block 128.
// ---------------------------------------------------------------------------
#define NSTG 8
#define A_BYTES (128 * 32)                  // 4 KB
#define B_BYTES (128 * 32)                  // 4 KB
#define STG_BYTES (A_BYTES + B_BYTES)       // 8 KB
#define SMEM_DYN (NSTG * STG_BYTES)         // 64 KB

template <bool MERGE, bool OUTH, bool RELU>
__global__ void __launch_bounds__(128, 2)
gemm_h(const __half* __restrict__ A0, const __half* __restrict__ B0, void* __restrict__ C0,
       const __half* __restrict__ A1, const __half* __restrict__ B1, void* __restrict__ C1,
       int lda, int ldb, int ldc, int nk, float alpha0, float alpha1,
       size_t sAz, size_t sBz, size_t sCz)
{
    const bool sel = MERGE && (blockIdx.z & 1);
    const __half* A = sel ? A1 : A0;
    const __half* B = sel ? B1 : B0;
    void* Cv        = sel ? C1 : C0;
    const float alpha = sel ? alpha1 : alpha0;
    const size_t zoff = MERGE ? 0 : (size_t)blockIdx.z;
    A += zoff * sAz;
    B += zoff * sBz;

    const int bm = blockIdx.y, bn = blockIdx.x;
    const int tid  = threadIdx.x;
    const int warp = tid >> 5;
    const int lane = tid & 31;
    const int wm   = warp >> 1;             // 0..1 : 64-row band
    const int wn   = warp & 1;              // 0..1 : 64-col band
    const int grp  = lane >> 2;             // 0..7
    const int tig  = lane & 3;              // 0..3

    extern __shared__ char dsm[];
    const uint32_t sb = smem_u32(dsm);

    // per-lane ldmatrix.x4 offsets (verified mapping, 64x64 warp tile)
    const int lT = lane >> 3, lr = lane & 7;
    uint32_t offA[4], offB[4];
    {
        const int am  = wm * 64 + (lT & 1) * 8 + lr;     // + mt*16
        const int akc = lT >> 1;
#pragma unroll
        for (int mt = 0; mt < 4; mt++) offA[mt] = swz(am + mt * 16, akc);
        const int bn0 = wn * 64 + ((lT >> 1) << 3) + lr; // + j*16
        const int bkc = lT & 1;
#pragma unroll
        for (int j = 0; j < 4; j++) offB[j] = (uint32_t)A_BYTES + swz(bn0 + j * 16, bkc);
    }

    const __half* Abase = A + (size_t)(bm * 128) * lda;
    const __half* Bbase = B + (size_t)(bn * 128) * ldb;

    auto load_stage = [&](int s, int kt) {
        const uint32_t st = sb + (uint32_t)(s * STG_BYTES);
        const int k0 = kt * 16;
#pragma unroll
        for (int i = 0; i < 2; i++) {        // A: 128 rows x 2 chunks = 256
            const int lin = tid + i * 128;
            const int row = lin >> 1, kc = lin & 1;
            cp16(st + swz(row, kc), Abase + (size_t)row * lda + k0 + kc * 8);
        }
#pragma unroll
        for (int i = 0; i < 2; i++) {        // B: 128 rows x 2 chunks = 256
            const int lin = tid + i * 128;
            const int row = lin >> 1, kc = lin & 1;
            cp16(st + A_BYTES + swz(row, kc), Bbase + (size_t)row * ldb + k0 + kc * 8);
        }
        cp_commit();
    };

    // prologue: stages 0..6 in flight
#pragma unroll
    for (int s = 0; s < 7; s++) load_stage(s, s);

    float acc[4][8][4] = {};

    for (int kt = 0; kt < nk; kt++) {
        const int rem = nk - 1 - kt;         // groups still loading after this stage
        if      (rem >= 6) cp_wait<6>();
        else if (rem == 5) cp_wait<5>();
        else if (rem == 4) cp_wait<4>();
        else if (rem == 3) cp_wait<3>();
        else if (rem == 2) cp_wait<2>();
        else if (rem == 1) cp_wait<1>();
        else               cp_wait<0>();
        __syncthreads();

        const uint32_t st = sb + (uint32_t)((kt & 7) * STG_BYTES);

        // fragments FIRST — don't queue them behind the refill on the LSU
        uint32_t a[4][4], b[8][2];
#pragma unroll
        for (int mt = 0; mt < 4; mt++)
            LDSM4(a[mt][0], a[mt][1], a[mt][2], a[mt][3], st + offA[mt]);
#pragma unroll
        for (int j = 0; j < 4; j++) {
            uint32_t r0, r1, r2, r3;
            LDSM4(r0, r1, r2, r3, st + offB[j]);
            b[2 * j][0] = r0; b[2 * j][1] = r1;
            b[2 * j + 1][0] = r2; b[2 * j + 1][1] = r3;
        }

        // refill 7 ahead — drains under the HMMA burst
        if (kt + 7 < nk) load_stage((kt + 7) & 7, kt + 7);

#pragma unroll
        for (int mt = 0; mt < 4; mt++)
#pragma unroll
            for (int nt = 0; nt < 8; nt++)
                mma_f16(acc[mt][nt], a[mt], b[nt]);
    }

    // ---- epilogue ----
    const int r0 = bm * 128 + wm * 64;
    const int c0 = bn * 128 + wn * 64;
#pragma unroll
    for (int mt = 0; mt < 4; mt++) {
#pragma unroll
        for (int nt = 0; nt < 8; nt++) {
            const int r = r0 + mt * 16 + grp;
            const int c = c0 + nt * 8 + tig * 2;
            float v0 = acc[mt][nt][0] * alpha;
            float v1 = acc[mt][nt][1] * alpha;
            float v2 = acc[mt][nt][2] * alpha;
            float v3 = acc[mt][nt][3] * alpha;
            if (RELU) {
                v0 = fmaxf(v0, 0.f); v1 = fmaxf(v1, 0.f);
                v2 = fmaxf(v2, 0.f); v3 = fmaxf(v3, 0.f);
            }
            if (OUTH) {
                __half* C = (__half*)Cv + zoff * sCz;
                *(__half2*)(C + (size_t)r * ldc + c)       = __floats2half2_rn(v0, v1);
                *(__half2*)(C + (size_t)(r + 8) * ldc + c) = __floats2half2_rn(v2, v3);
            } else {
                float* C = (float*)Cv + zoff * sCz;
                *(float2*)(C + (size_t)r * ldc + c)       = make_float2(v0, v1);
                *(float2*)(C + (size_t)(r + 8) * ldc + c) = make_float2(v2, v3);
            }
        }
    }
}

// ---------------------------------------------------------------------------
// Prep: fp32 -> fp16 for x1 and x2 in one launch (blockIdx.y selects)
// ---------------------------------------------------------------------------
__global__ void __launch_bounds__(256)
f2h_two(const float4* __restrict__ s1, __half2* __restrict__ d1,
        const float4* __restrict__ s2, __half2* __restrict__ d2, int n4)
{
    const int i = blockIdx.x * 256 + threadIdx.x;
    if (i >= n4) return;
    const float4* s = blockIdx.y ? s2 : s1;
    __half2*      d = blockIdx.y ? d2 : d1;
    const float4 v = s[i];
    d[2 * i]     = __floats2half2_rn(v.x, v.y);
    d[2 * i + 1] = __floats2half2_rn(v.z, v.w);
}

// 4 weight transposes (to K-major) + fp16 convert in one launch (blockIdx.z)
__global__ void __launch_bounds__(256)
transpose_h4(const float* __restrict__ w0, const float* __restrict__ w1,
             const float* __restrict__ w2, const float* __restrict__ w3,
             __half* __restrict__ t0, __half* __restrict__ t1,
             __half* __restrict__ t2, __half* __restrict__ t3)
{
    const float* w = (blockIdx.z == 0) ? w0 : (blockIdx.z == 1) ? w1
                   : (blockIdx.z == 2) ? w2 : w3;
    __half* wt     = (blockIdx.z == 0) ? t0 : (blockIdx.z == 1) ? t1
                   : (blockIdx.z == 2) ? t2 : t3;

    __shared__ float t[32][33];
    const int bx = blockIdx.x * 32, by = blockIdx.y * 32;
    const int x = threadIdx.x & 31, y4 = threadIdx.x >> 5;
#pragma unroll
    for (int i = 0; i < 32; i += 8)
        t[y4 + i][x] = w[(size_t)(by + y4 + i) * DD + bx + x];
    __syncthreads();
#pragma unroll
    for (int i = 0; i < 32; i += 8)
        wt[(size_t)(bx + y4 + i) * DD + by + x] = __float2half_rn(t[x][y4 + i]);
}

// ---------------------------------------------------------------------------
// Row softmax with additive mask on fp16 P (compute fp32, store fp16)
// ---------------------------------------------------------------------------
__global__ void __launch_bounds__(256)
softmax_mask(__half* __restrict__ P, const int* __restrict__ mask)
{
    const int row = blockIdx.x;
    const int b   = row >> 11;
    __half* p = P + (size_t)row * SS;
    const int* mrow = mask + (size_t)b * SS;

    const int tid = threadIdx.x, lane = tid & 31, warp = tid >> 5;
    __shared__ float red[8];

    float v[8];
    float mx = -INFINITY;
#pragma unroll
    for (int i = 0; i < 8; i++) {
        const int j = tid + i * 256;
        float x = __half2float(p[j]);
        if (mrow[j]) x -= 1.0e9f;
        v[i] = x;
        mx = fmaxf(mx, x);
    }
#pragma unroll
    for (int o = 16; o; o >>= 1) mx = fmaxf(mx, __shfl_xor_sync(0xffffffffu, mx, o));
    if (lane == 0) red[warp] = mx;
    __syncthreads();
    mx = red[0];
#pragma unroll
    for (int w = 1; w < 8; w++) mx = fmaxf(mx, red[w]);

    float s = 0.f;
#pragma unroll
    for (int i = 0; i < 8; i++) {
        const float e = __expf(v[i] - mx);
        v[i] = e;
        s += e;
    }
    __syncthreads();
#pragma unroll
    for (int o = 16; o; o >>= 1) s += __shfl_xor_sync(0xffffffffu, s, o);
    if (lane == 0) red[warp] = s;
    __syncthreads();
    s = red[0];
#pragma unroll
    for (int w = 1; w < 8; w++) s += red[w];

    const float inv = 1.0f / s;
#pragma unroll
    for (int i = 0; i < 8; i++) p[tid + i * 256] = __float2half_rn(v[i] * inv);
}

// ---------------------------------------------------------------------------
// Launch
// ---------------------------------------------------------------------------
extern "C" void kernel_launch(void* const* d_in, const int* in_sizes, int n_in,
                              void* d_out, int out_size)
{
    (void)in_sizes; (void)n_in; (void)out_size;

    const float* x1      = (const float*)d_in[0];
    const float* x2      = (const float*)d_in[1];
    const int*   maskSeq = (const int*)  d_in[2];
    const float* wq      = (const float*)d_in[3];
    const float* wk      = (const float*)d_in[4];
    const float* wv      = (const float*)d_in[5];
    const float* wo      = (const float*)d_in[6];
    float* out = (float*)d_out;

    __half *x1h, *x2h, *wqT, *wkT, *wvT, *woT, *Q, *Kp, *Vt, *P, *Y;
    cudaGetSymbolAddress((void**)&x1h, g_x1h);
    cudaGetSymbolAddress((void**)&x2h, g_x2h);
    cudaGetSymbolAddress((void**)&wqT, g_wqT);
    cudaGetSymbolAddress((void**)&wkT, g_wkT);
    cudaGetSymbolAddress((void**)&wvT, g_wvT);
    cudaGetSymbolAddress((void**)&woT, g_woT);
    cudaGetSymbolAddress((void**)&Q,   g_Q);
    cudaGetSymbolAddress((void**)&Kp,  g_K);
    cudaGetSymbolAddress((void**)&Vt,  g_Vt);
    cudaGetSymbolAddress((void**)&P,   g_P);
    cudaGetSymbolAddress((void**)&Y,   g_Y);

    cudaFuncSetAttribute(gemm_h<true,  true,  false>, cudaFuncAttributeMaxDynamicSharedMemorySize, SMEM_DYN);
    cudaFuncSetAttribute(gemm_h<false, true,  false>, cudaFuncAttributeMaxDynamicSharedMemorySize, SMEM_DYN);
    cudaFuncSetAttribute(gemm_h<false, true,  true >, cudaFuncAttributeMaxDynamicSharedMemorySize, SMEM_DYN);
    cudaFuncSetAttribute(gemm_h<false, false, false>, cudaFuncAttributeMaxDynamicSharedMemorySize, SMEM_DYN);

    const float scale = 0.03125f;   // 1024^-0.5
    const int n4 = (MTOT * DD) / 4;

    // prep (2 launches)
    f2h_two<<<dim3(n4 / 256, 2), 256>>>((const float4*)x1, (__half2*)x1h,
                                        (const float4*)x2, (__half2*)x2h, n4);
    transpose_h4<<<dim3(32, 32, 4), 256>>>(wq, wk, wv, wo, wqT, wkT, wvT, woT);

    // merged: Q = h(scale * x1 @ wq)  and  K = h(x2 @ wk)
    gemm_h<true, true, false><<<dim3(DD / 128, MTOT / 128, 2), 128, SMEM_DYN>>>(
        x1h, wqT, Q, x2h, wkT, Kp, DD, DD, DD, DD / 16, scale, 1.f, 0, 0, 0);

    // Vt[e, s] = h( sum_d wvT[e,d] * x2h[s,d] )   (V transposed, K-major for PV)
    gemm_h<false, true, false><<<dim3(MTOT / 128, DD / 128, 1), 128, SMEM_DYN>>>(
        wvT, x2h, Vt, wvT, x2h, Vt, DD, DD, MTOT, DD / 16, 1.f, 1.f, 0, 0, 0);

    // P = Q @ K^T  (per batch)
    gemm_h<false, true, false><<<dim3(SS / 128, SS / 128, BB), 128, SMEM_DYN>>>(
        Q, Kp, P, Q, Kp, P, DD, DD, SS, DD / 16, 1.f, 1.f,
        (size_t)SS * DD, (size_t)SS * DD, (size_t)SS * SS);

    // mask + softmax (in place, fp16)
    softmax_mask<<<BB * SS, 256>>>(P, maskSeq);

    // Y = h(relu(P @ Vt^T))  (per batch; Vt batch slice via column offset)
    gemm_h<false, true, true><<<dim3(DD / 128, SS / 128, BB), 128, SMEM_DYN>>>(
        P, Vt, Y, P, Vt, Y, SS, MTOT, DD, SS / 16, 1.f, 1.f,
        (size_t)SS * SS, (size_t)SS, (size_t)SS * DD);

    // out = Y @ wo (fp32 out)
    gemm_h<false, false, false><<<dim3(DD / 128, MTOT / 128, 1), 128, SMEM_DYN>>>(
        Y, woT, out, Y, woT, out, DD, DD, DD, DD / 16, 1.f, 1.f, 0, 0, 0);
}

// round 16
// speedup vs baseline: 1.3237x; 1.0590x over previous
#include <cuda_runtime.h>
#include <cuda_fp16.h>
#include <cstdint>
#include <math.h>

#define DEV_INLINE __device__ __forceinline__

#define BB 8
#define SS 2048
#define DD 1024
#define MTOT (BB * SS)   // 16384

// ---------------------------------------------------------------------------
// Scratch (__device__ globals; allocation-free rule). 16B aligned for cp.async.
// ---------------------------------------------------------------------------
__device__ __align__(16) __half g_x1h[(size_t)MTOT * DD];
__device__ __align__(16) __half g_x2h[(size_t)MTOT * DD];
__device__ __align__(16) __half g_wqT[DD * DD];
__device__ __align__(16) __half g_wkT[DD * DD];
__device__ __align__(16) __half g_wvT[DD * DD];
__device__ __align__(16) __half g_woT[DD * DD];
__device__ __align__(16) __half g_Q [(size_t)MTOT * DD];
__device__ __align__(16) __half g_K [(size_t)MTOT * DD];
__device__ __align__(16) __half g_Vt[(size_t)DD * MTOT];       // [D, B*S]
__device__ __align__(16) __half g_P [(size_t)BB * SS * SS];
__device__ __align__(16) __half g_Y [(size_t)MTOT * DD];

// ---------------------------------------------------------------------------
// Helpers
// ---------------------------------------------------------------------------
DEV_INLINE uint32_t smem_u32(const void* p) {
    uint32_t a;
    asm("{ .reg .u64 t; cvta.to.shared.u64 t, %1; cvt.u32.u64 %0, t; }" : "=r"(a) : "l"(p));
    return a;
}
DEV_INLINE void cp16(uint32_t s, const void* g) {
    asm volatile("cp.async.cg.shared.global [%0], [%1], 16;" :: "r"(s), "l"(g));
}
DEV_INLINE void cp_commit() { asm volatile("cp.async.commit_group;" ::: "memory"); }
template <int N> DEV_INLINE void cp_wait() {
    asm volatile("cp.async.wait_group %0;" :: "n"(N) : "memory");
}

#define LDSM4(R0, R1, R2, R3, addr)                                           \
    asm volatile("ldmatrix.sync.aligned.m8n8.x4.shared.b16 {%0,%1,%2,%3}, [%4];" \
                 : "=r"(R0), "=r"(R1), "=r"(R2), "=r"(R3) : "r"(addr))

DEV_INLINE void mma_f16(float* d, const uint32_t* a, const uint32_t* b) {
    asm volatile(
        "mma.sync.aligned.m16n8k16.row.col.f32.f16.f16.f32 "
        "{%0,%1,%2,%3}, {%4,%5,%6,%7}, {%8,%9}, {%0,%1,%2,%3};\n"
        : "+f"(d[0]), "+f"(d[1]), "+f"(d[2]), "+f"(d[3])
        : "r"(a[0]), "r"(a[1]), "r"(a[2]), "r"(a[3]),
          "r"(b[0]), "r"(b[1]));
}

// swizzled byte offset of 16B chunk (row, kc) in a k16 tile with 32B rows
DEV_INLINE uint32_t swz(int row, int kc) {
    return (uint32_t)(row * 32 + ((kc ^ ((row >> 2) & 1)) << 4));
}

// ---------------------------------------------------------------------------
// FP16 tensor-core GEMM — EXACT R10 configuration (best: 854us, tensor 52%).
// CTA tile 128x128, 4 warps (2 M x 2 N), warp tile 64x64, k-step 16.
// 6-stage cp.async pipeline (48KB) -> 2 CTAs/SM; single-buffered fragments.
// MERGE: blockIdx.z selects operand set 0/1. OUTH: store __half; else fp32.
// Grid: (N/128, M/128, z), block 128.
// ---------------------------------------------------------------------------
#define NSTG 6
#define A_BYTES (128 * 32)                  // 4 KB
#define B_BYTES (128 * 32)                  // 4 KB
#define STG_BYTES (A_BYTES + B_BYTES)       // 8 KB
#define SMEM_DYN (NSTG * STG_BYTES)         // 48 KB

template <bool MERGE, bool OUTH, bool RELU>
__global__ void __launch_bounds__(128, 2)
gemm_h(const __half* __restrict__ A0, const __half* __restrict__ B0, void* __restrict__ C0,
       const __half* __restrict__ A1, const __half* __restrict__ B1, void* __restrict__ C1,
       int lda, int ldb, int ldc, int nk, float alpha0, float alpha1,
       size_t sAz, size_t sBz, size_t sCz)
{
    const bool sel = MERGE && (blockIdx.z & 1);
    const __half* A = sel ? A1 : A0;
    const __half* B = sel ? B1 : B0;
    void* Cv        = sel ? C1 : C0;
    const float alpha = sel ? alpha1 : alpha0;
    const size_t zoff = MERGE ? 0 : (size_t)blockIdx.z;
    A += zoff * sAz;
    B += zoff * sBz;

    const int bm = blockIdx.y, bn = blockIdx.x;
    const int tid  = threadIdx.x;
    const int warp = tid >> 5;
    const int lane = tid & 31;
    const int wm   = warp >> 1;             // 0..1 : 64-row band
    const int wn   = warp & 1;              // 0..1 : 64-col band
    const int grp  = lane >> 2;             // 0..7
    const int tig  = lane & 3;              // 0..3

    extern __shared__ char dsm[];
    const uint32_t sb = smem_u32(dsm);

    // per-lane ldmatrix.x4 offsets (verified mapping, 64x64 warp tile)
    const int lT = lane >> 3, lr = lane & 7;
    uint32_t offA[4], offB[4];
    {
        const int am  = wm * 64 + (lT & 1) * 8 + lr;     // + mt*16
        const int akc = lT >> 1;
#pragma unroll
        for (int mt = 0; mt < 4; mt++) offA[mt] = swz(am + mt * 16, akc);
        const int bn0 = wn * 64 + ((lT >> 1) << 3) + lr; // + j*16
        const int bkc = lT & 1;
#pragma unroll
        for (int j = 0; j < 4; j++) offB[j] = (uint32_t)A_BYTES + swz(bn0 + j * 16, bkc);
    }

    const __half* Abase = A + (size_t)(bm * 128) * lda;
    const __half* Bbase = B + (size_t)(bn * 128) * ldb;

    auto load_stage = [&](int s, int kt) {
        const uint32_t st = sb + (uint32_t)(s * STG_BYTES);
        const int k0 = kt * 16;
#pragma unroll
        for (int i = 0; i < 2; i++) {        // A: 128 rows x 2 chunks = 256
            const int lin = tid + i * 128;
            const int row = lin >> 1, kc = lin & 1;
            cp16(st + swz(row, kc), Abase + (size_t)row * lda + k0 + kc * 8);
        }
#pragma unroll
        for (int i = 0; i < 2; i++) {        // B: 128 rows x 2 chunks = 256
            const int lin = tid + i * 128;
            const int row = lin >> 1, kc = lin & 1;
            cp16(st + A_BYTES + swz(row, kc), Bbase + (size_t)row * ldb + k0 + kc * 8);
        }
        cp_commit();
    };

    // prologue: stages 0..4 in flight
#pragma unroll
    for (int s = 0; s < 5; s++) load_stage(s, s);

    float acc[4][8][4] = {};

    int sl = 5;                              // next stage slot to fill
    for (int kt = 0; kt < nk; kt++) {
        const int rem = nk - 1 - kt;
        if      (rem >= 4) cp_wait<4>();
        else if (rem == 3) cp_wait<3>();
        else if (rem == 2) cp_wait<2>();
        else if (rem == 1) cp_wait<1>();
        else               cp_wait<0>();
        __syncthreads();

        if (kt + 5 < nk) {
            load_stage(sl, kt + 5);
            if (++sl == NSTG) sl = 0;
        }

        const int cs = kt % NSTG;
        const uint32_t st = sb + (uint32_t)(cs * STG_BYTES);

        uint32_t a[4][4], b[8][2];
#pragma unroll
        for (int mt = 0; mt < 4; mt++)
            LDSM4(a[mt][0], a[mt][1], a[mt][2], a[mt][3], st + offA[mt]);
#pragma unroll
        for (int j = 0; j < 4; j++) {
            uint32_t r0, r1, r2, r3;
            LDSM4(r0, r1, r2, r3, st + offB[j]);
            b[2 * j][0] = r0; b[2 * j][1] = r1;
            b[2 * j + 1][0] = r2; b[2 * j + 1][1] = r3;
        }
#pragma unroll
        for (int mt = 0; mt < 4; mt++)
#pragma unroll
            for (int nt = 0; nt < 8; nt++)
                mma_f16(acc[mt][nt], a[mt], b[nt]);
    }

    // ---- epilogue ----
    const int r0 = bm * 128 + wm * 64;
    const int c0 = bn * 128 + wn * 64;
#pragma unroll
    for (int mt = 0; mt < 4; mt++) {
#pragma unroll
        for (int nt = 0; nt < 8; nt++) {
            const int r = r0 + mt * 16 + grp;
            const int c = c0 + nt * 8 + tig * 2;
            float v0 = acc[mt][nt][0] * alpha;
            float v1 = acc[mt][nt][1] * alpha;
            float v2 = acc[mt][nt][2] * alpha;
            float v3 = acc[mt][nt][3] * alpha;
            if (RELU) {
                v0 = fmaxf(v0, 0.f); v1 = fmaxf(v1, 0.f);
                v2 = fmaxf(v2, 0.f); v3 = fmaxf(v3, 0.f);
            }
            if (OUTH) {
                __half* C = (__half*)Cv + zoff * sCz;
                *(__half2*)(C + (size_t)r * ldc + c)       = __floats2half2_rn(v0, v1);
                *(__half2*)(C + (size_t)(r + 8) * ldc + c) = __floats2half2_rn(v2, v3);
            } else {
                float* C = (float*)Cv + zoff * sCz;
                *(float2*)(C + (size_t)r * ldc + c)       = make_float2(v0, v1);
                *(float2*)(C + (size_t)(r + 8) * ldc + c) = make_float2(v2, v3);
            }
        }
    }
}

// ---------------------------------------------------------------------------
// Prep: fp32 -> fp16 for x1 and x2 in one launch (blockIdx.y selects)
// ---------------------------------------------------------------------------
__global__ void __launch_bounds__(256)
f2h_two(const float4* __restrict__ s1, __half2* __restrict__ d1,
        const float4* __restrict__ s2, __half2* __restrict__ d2, int n4)
{
    const int i = blockIdx.x * 256 + threadIdx.x;
    if (i >= n4) return;
    const float4* s = blockIdx.y ? s2 : s1;
    __half2*      d = blockIdx.y ? d2 : d1;
    const float4 v = s[i];
    d[2 * i]     = __floats2half2_rn(v.x, v.y);
    d[2 * i + 1] = __floats2half2_rn(v.z, v.w);
}

// 4 weight transposes (to K-major) + fp16 convert in one launch (blockIdx.z)
__global__ void __launch_bounds__(256)
transpose_h4(const float* __restrict__ w0, const float* __restrict__ w1,
             const float* __restrict__ w2, const float* __restrict__ w3,
             __half* __restrict__ t0, __half* __restrict__ t1,
             __half* __restrict__ t2, __half* __restrict__ t3)
{
    const float* w = (blockIdx.z == 0) ? w0 : (blockIdx.z == 1) ? w1
                   : (blockIdx.z == 2) ? w2 : w3;
    __half* wt     = (blockIdx.z == 0) ? t0 : (blockIdx.z == 1) ? t1
                   : (blockIdx.z == 2) ? t2 : t3;

    __shared__ float t[32][33];
    const int bx = blockIdx.x * 32, by = blockIdx.y * 32;
    const int x = threadIdx.x & 31, y4 = threadIdx.x >> 5;
#pragma unroll
    for (int i = 0; i < 32; i += 8)
        t[y4 + i][x] = w[(size_t)(by + y4 + i) * DD + bx + x];
    __syncthreads();
#pragma unroll
    for (int i = 0; i < 32; i += 8)
        wt[(size_t)(bx + y4 + i) * DD + by + x] = __float2half_rn(t[x][y4 + i]);
}

// ---------------------------------------------------------------------------
// Warp-per-row softmax with additive mask on fp16 P.
// 8 rows per 256-thread block; each lane owns 64 elements via 8x int4 (16B)
// vectorized loads; reductions are pure shfl (no __syncthreads).
// ---------------------------------------------------------------------------
__global__ void __launch_bounds__(256)
softmax_mask(__half* __restrict__ P, const int* __restrict__ mask)
{
    const int row  = blockIdx.x * 8 + (threadIdx.x >> 5);
    const int lane = threadIdx.x & 31;
    const int b    = row >> 11;
    int4* prow = (int4*)(P + (size_t)row * SS);            // 256 chunks of 8 halves
    const int4* mrow = (const int4*)(mask + (size_t)b * SS); // 512 chunks of 4 ints

    float v[64];
    float mx = -INFINITY;
#pragma unroll
    for (int i = 0; i < 8; i++) {
        const int c = lane + i * 32;                        // chunk 0..255
        int4 pk = prow[c];
        const int4 m0 = mrow[2 * c];
        const int4 m1 = mrow[2 * c + 1];
        const int mAll[8] = { m0.x, m0.y, m0.z, m0.w, m1.x, m1.y, m1.z, m1.w };
        const __half2* h = (const __half2*)&pk;
#pragma unroll
        for (int j = 0; j < 4; j++) {
            float2 f = __half22float2(h[j]);
            if (mAll[2 * j])     f.x -= 1.0e9f;
            if (mAll[2 * j + 1]) f.y -= 1.0e9f;
            v[i * 8 + 2 * j]     = f.x;
            v[i * 8 + 2 * j + 1] = f.y;
            mx = fmaxf(mx, fmaxf(f.x, f.y));
        }
    }
#pragma unroll
    for (int o = 16; o; o >>= 1) mx = fmaxf(mx, __shfl_xor_sync(0xffffffffu, mx, o));

    float s = 0.f;
#pragma unroll
    for (int i = 0; i < 64; i++) {
        const float e = __expf(v[i] - mx);
        v[i] = e;
        s += e;
    }
#pragma unroll
    for (int o = 16; o; o >>= 1) s += __shfl_xor_sync(0xffffffffu, s, o);

    const float inv = 1.0f / s;
#pragma unroll
    for (int i = 0; i < 8; i++) {
        int4 pk;
        __half2* h = (__half2*)&pk;
#pragma unroll
        for (int j = 0; j < 4; j++)
            h[j] = __floats2half2_rn(v[i * 8 + 2 * j] * inv, v[i * 8 + 2 * j + 1] * inv);
        prow[lane + i * 32] = pk;
    }
}

// ---------------------------------------------------------------------------
// Launch
// ---------------------------------------------------------------------------
extern "C" void kernel_launch(void* const* d_in, const int* in_sizes, int n_in,
                              void* d_out, int out_size)
{
    (void)in_sizes; (void)n_in; (void)out_size;

    const float* x1      = (const float*)d_in[0];
    const float* x2      = (const float*)d_in[1];
    const int*   maskSeq = (const int*)  d_in[2];
    const float* wq      = (const float*)d_in[3];
    const float* wk      = (const float*)d_in[4];
    const float* wv      = (const float*)d_in[5];
    const float* wo      = (const float*)d_in[6];
    float* out = (float*)d_out;

    __half *x1h, *x2h, *wqT, *wkT, *wvT, *woT, *Q, *Kp, *Vt, *P, *Y;
    cudaGetSymbolAddress((void**)&x1h, g_x1h);
    cudaGetSymbolAddress((void**)&x2h, g_x2h);
    cudaGetSymbolAddress((void**)&wqT, g_wqT);
    cudaGetSymbolAddress((void**)&wkT, g_wkT);
    cudaGetSymbolAddress((void**)&wvT, g_wvT);
    cudaGetSymbolAddress((void**)&woT, g_woT);
    cudaGetSymbolAddress((void**)&Q,   g_Q);
    cudaGetSymbolAddress((void**)&Kp,  g_K);
    cudaGetSymbolAddress((void**)&Vt,  g_Vt);
    cudaGetSymbolAddress((void**)&P,   g_P);
    cudaGetSymbolAddress((void**)&Y,   g_Y);

    cudaFuncSetAttribute(gemm_h<true,  true,  false>, cudaFuncAttributeMaxDynamicSharedMemorySize, SMEM_DYN);
    cudaFuncSetAttribute(gemm_h<false, true,  false>, cudaFuncAttributeMaxDynamicSharedMemorySize, SMEM_DYN);
    cudaFuncSetAttribute(gemm_h<false, true,  true >, cudaFuncAttributeMaxDynamicSharedMemorySize, SMEM_DYN);
    cudaFuncSetAttribute(gemm_h<false, false, false>, cudaFuncAttributeMaxDynamicSharedMemorySize, SMEM_DYN);

    const float scale = 0.03125f;   // 1024^-0.5
    const int n4 = (MTOT * DD) / 4;

    // prep (2 launches)
    f2h_two<<<dim3(n4 / 256, 2), 256>>>((const float4*)x1, (__half2*)x1h,
                                        (const float4*)x2, (__half2*)x2h, n4);
    transpose_h4<<<dim3(32, 32, 4), 256>>>(wq, wk, wv, wo, wqT, wkT, wvT, woT);

    // merged: Q = h(scale * x1 @ wq)  and  K = h(x2 @ wk)
    gemm_h<true, true, false><<<dim3(DD / 128, MTOT / 128, 2), 128, SMEM_DYN>>>(
        x1h, wqT, Q, x2h, wkT, Kp, DD, DD, DD, DD / 16, scale, 1.f, 0, 0, 0);

    // Vt[e, s] = h( sum_d wvT[e,d] * x2h[s,d] )   (V transposed, K-major for PV)
    gemm_h<false, true, false><<<dim3(MTOT / 128, DD / 128, 1), 128, SMEM_DYN>>>(
        wvT, x2h, Vt, wvT, x2h, Vt, DD, DD, MTOT, DD / 16, 1.f, 1.f, 0, 0, 0);

    // P = Q @ K^T  (per batch)
    gemm_h<false, true, false><<<dim3(SS / 128, SS / 128, BB), 128, SMEM_DYN>>>(
        Q, Kp, P, Q, Kp, P, DD, DD, SS, DD / 16, 1.f, 1.f,
        (size_t)SS * DD, (size_t)SS * DD, (size_t)SS * SS);

    // mask + softmax (in place, fp16; warp per row)
    softmax_mask<<<(BB * SS) / 8, 256>>>(P, maskSeq);

    // Y = h(relu(P @ Vt^T))  (per batch; Vt batch slice via column offset)
    gemm_h<false, true, true><<<dim3(DD / 128, SS / 128, BB), 128, SMEM_DYN>>>(
        P, Vt, Y, P, Vt, Y, SS, MTOT, DD, SS / 16, 1.f, 1.f,
        (size_t)SS * SS, (size_t)SS, (size_t)SS * DD);

    // out = Y @ wo (fp32 out)
    gemm_h<false, false, false><<<dim3(DD / 128, MTOT / 128, 1), 128, SMEM_DYN>>>(
        Y, woT, out, Y, woT, out, DD, DD, DD, DD / 16, 1.f, 1.f, 0, 0, 0);
}

// round 17
// speedup vs baseline: 1.3507x; 1.0204x over previous
#include <cuda_runtime.h>
#include <cuda_fp16.h>
#include <cstdint>
#include <math.h>

#define DEV_INLINE __device__ __forceinline__

#define BB 8
#define SS 2048
#define DD 1024
#define MTOT (BB * SS)   // 16384

// ---------------------------------------------------------------------------
// Scratch (__device__ globals; allocation-free rule). 16B aligned for cp.async.
// ---------------------------------------------------------------------------
__device__ __align__(16) __half g_x1h[(size_t)MTOT * DD];
__device__ __align__(16) __half g_x2h[(size_t)MTOT * DD];
__device__ __align__(16) __half g_wqT[DD * DD];
__device__ __align__(16) __half g_wkT[DD * DD];
__device__ __align__(16) __half g_wvT[DD * DD];
__device__ __align__(16) __half g_woT[DD * DD];
__device__ __align__(16) __half g_Q [(size_t)MTOT * DD];
__device__ __align__(16) __half g_K [(size_t)MTOT * DD];
__device__ __align__(16) __half g_Vt[(size_t)DD * MTOT];       // [D, B*S]
__device__ __align__(16) __half g_P [(size_t)BB * SS * SS];
__device__ __align__(16) __half g_Y [(size_t)MTOT * DD];

// ---------------------------------------------------------------------------
// Helpers
// ---------------------------------------------------------------------------
DEV_INLINE uint32_t smem_u32(const void* p) {
    uint32_t a;
    asm("{ .reg .u64 t; cvta.to.shared.u64 t, %1; cvt.u32.u64 %0, t; }" : "=r"(a) : "l"(p));
    return a;
}
DEV_INLINE void cp16(uint32_t s, const void* g) {
    asm volatile("cp.async.cg.shared.global [%0], [%1], 16;" :: "r"(s), "l"(g));
}
DEV_INLINE void cp_commit() { asm volatile("cp.async.commit_group;" ::: "memory"); }
template <int N> DEV_INLINE void cp_wait() {
    asm volatile("cp.async.wait_group %0;" :: "n"(N) : "memory");
}

#define LDSM4(R0, R1, R2, R3, addr)                                           \
    asm volatile("ldmatrix.sync.aligned.m8n8.x4.shared.b16 {%0,%1,%2,%3}, [%4];" \
                 : "=r"(R0), "=r"(R1), "=r"(R2), "=r"(R3) : "r"(addr))

DEV_INLINE void mma_f16(float* d, const uint32_t* a, const uint32_t* b) {
    asm volatile(
        "mma.sync.aligned.m16n8k16.row.col.f32.f16.f16.f32 "
        "{%0,%1,%2,%3}, {%4,%5,%6,%7}, {%8,%9}, {%0,%1,%2,%3};\n"
        : "+f"(d[0]), "+f"(d[1]), "+f"(d[2]), "+f"(d[3])
        : "r"(a[0]), "r"(a[1]), "r"(a[2]), "r"(a[3]),
          "r"(b[0]), "r"(b[1]));
}

// swizzled byte offset of 16B chunk (row, kc) in a k16 tile with 32B rows
DEV_INLINE uint32_t swz(int row, int kc) {
    return (uint32_t)(row * 32 + ((kc ^ ((row >> 2) & 1)) << 4));
}

// ---------------------------------------------------------------------------
// GEMM core — EXACT R10 inner loop (best: 854us, tensor 52%, regs 190).
// C[128,128] tile = alpha * A[M,K] @ B[N,K]^T  (K-major fp16 operands).
// 4 warps (2 M x 2 N), warp tile 64x64, k-step 16, 6-stage cp.async (48KB),
// 2 CTAs/SM, single-buffered fragments.
// ---------------------------------------------------------------------------
#define NSTG 6
#define A_BYTES (128 * 32)                  // 4 KB
#define B_BYTES (128 * 32)                  // 4 KB
#define STG_BYTES (A_BYTES + B_BYTES)       // 8 KB
#define SMEM_DYN (NSTG * STG_BYTES)         // 48 KB

template <bool OUTH, bool RELU>
DEV_INLINE void gemm_core(const __half* __restrict__ A, const __half* __restrict__ B,
                          void* __restrict__ Cv,
                          int lda, int ldb, int ldc, int nk, float alpha,
                          int bm, int bn, char* dsm)
{
    const int tid  = threadIdx.x;
    const int warp = tid >> 5;
    const int lane = tid & 31;
    const int wm   = warp >> 1;             // 0..1 : 64-row band
    const int wn   = warp & 1;              // 0..1 : 64-col band
    const int grp  = lane >> 2;             // 0..7
    const int tig  = lane & 3;              // 0..3

    const uint32_t sb = smem_u32(dsm);

    // per-lane ldmatrix.x4 offsets (verified mapping, 64x64 warp tile)
    const int lT = lane >> 3, lr = lane & 7;
    uint32_t offA[4], offB[4];
    {
        const int am  = wm * 64 + (lT & 1) * 8 + lr;     // + mt*16
        const int akc = lT >> 1;
#pragma unroll
        for (int mt = 0; mt < 4; mt++) offA[mt] = swz(am + mt * 16, akc);
        const int bn0 = wn * 64 + ((lT >> 1) << 3) + lr; // + j*16
        const int bkc = lT & 1;
#pragma unroll
        for (int j = 0; j < 4; j++) offB[j] = (uint32_t)A_BYTES + swz(bn0 + j * 16, bkc);
    }

    const __half* Abase = A + (size_t)(bm * 128) * lda;
    const __half* Bbase = B + (size_t)(bn * 128) * ldb;

    auto load_stage = [&](int s, int kt) {
        const uint32_t st = sb + (uint32_t)(s * STG_BYTES);
        const int k0 = kt * 16;
#pragma unroll
        for (int i = 0; i < 2; i++) {        // A: 128 rows x 2 chunks = 256
            const int lin = tid + i * 128;
            const int row = lin >> 1, kc = lin & 1;
            cp16(st + swz(row, kc), Abase + (size_t)row * lda + k0 + kc * 8);
        }
#pragma unroll
        for (int i = 0; i < 2; i++) {        // B: 128 rows x 2 chunks = 256
            const int lin = tid + i * 128;
            const int row = lin >> 1, kc = lin & 1;
            cp16(st + A_BYTES + swz(row, kc), Bbase + (size_t)row * ldb + k0 + kc * 8);
        }
        cp_commit();
    };

    // prologue: stages 0..4 in flight
#pragma unroll
    for (int s = 0; s < 5; s++) load_stage(s, s);

    float acc[4][8][4] = {};

    int sl = 5;                              // next stage slot to fill
    for (int kt = 0; kt < nk; kt++) {
        const int rem = nk - 1 - kt;
        if      (rem >= 4) cp_wait<4>();
        else if (rem == 3) cp_wait<3>();
        else if (rem == 2) cp_wait<2>();
        else if (rem == 1) cp_wait<1>();
        else               cp_wait<0>();
        __syncthreads();

        if (kt + 5 < nk) {
            load_stage(sl, kt + 5);
            if (++sl == NSTG) sl = 0;
        }

        const int cs = kt % NSTG;
        const uint32_t st = sb + (uint32_t)(cs * STG_BYTES);

        uint32_t a[4][4], b[8][2];
#pragma unroll
        for (int mt = 0; mt < 4; mt++)
            LDSM4(a[mt][0], a[mt][1], a[mt][2], a[mt][3], st + offA[mt]);
#pragma unroll
        for (int j = 0; j < 4; j++) {
            uint32_t r0, r1, r2, r3;
            LDSM4(r0, r1, r2, r3, st + offB[j]);
            b[2 * j][0] = r0; b[2 * j][1] = r1;
            b[2 * j + 1][0] = r2; b[2 * j + 1][1] = r3;
        }
#pragma unroll
        for (int mt = 0; mt < 4; mt++)
#pragma unroll
            for (int nt = 0; nt < 8; nt++)
                mma_f16(acc[mt][nt], a[mt], b[nt]);
    }

    // ---- epilogue ----
    const int r0 = bm * 128 + wm * 64;
    const int c0 = bn * 128 + wn * 64;
#pragma unroll
    for (int mt = 0; mt < 4; mt++) {
#pragma unroll
        for (int nt = 0; nt < 8; nt++) {
            const int r = r0 + mt * 16 + grp;
            const int c = c0 + nt * 8 + tig * 2;
            float v0 = acc[mt][nt][0] * alpha;
            float v1 = acc[mt][nt][1] * alpha;
            float v2 = acc[mt][nt][2] * alpha;
            float v3 = acc[mt][nt][3] * alpha;
            if (RELU) {
                v0 = fmaxf(v0, 0.f); v1 = fmaxf(v1, 0.f);
                v2 = fmaxf(v2, 0.f); v3 = fmaxf(v3, 0.f);
            }
            if (OUTH) {
                __half* C = (__half*)Cv;
                *(__half2*)(C + (size_t)r * ldc + c)       = __floats2half2_rn(v0, v1);
                *(__half2*)(C + (size_t)(r + 8) * ldc + c) = __floats2half2_rn(v2, v3);
            } else {
                float* C = (float*)Cv;
                *(float2*)(C + (size_t)r * ldc + c)       = make_float2(v0, v1);
                *(float2*)(C + (size_t)(r + 8) * ldc + c) = make_float2(v2, v3);
            }
        }
    }
}

// ---------------------------------------------------------------------------
// Thin kernels over gemm_core
// ---------------------------------------------------------------------------
// QK projections: z=0 -> Q = h(scale * x1 @ wq); z=1 -> K = h(x2 @ wk).
__global__ void __launch_bounds__(128, 2)
gemm_qk(const __half* __restrict__ x1h, const __half* __restrict__ wqT, __half* __restrict__ Q,
        const __half* __restrict__ x2h, const __half* __restrict__ wkT, __half* __restrict__ Kp,
        float scale)
{
    extern __shared__ char dsm[];
    const bool sel = blockIdx.z & 1;
    gemm_core<true, false>(sel ? x2h : x1h, sel ? wkT : wqT, sel ? Kp : Q,
                           DD, DD, DD, DD / 16, sel ? 1.f : scale,
                           blockIdx.y, blockIdx.x, dsm);
}

// Merged launch: z=0..7 -> P_z = Q_z @ K_z^T;  z=8..11 -> Vt = wvT @ x2h^T.
// Vt blocks backfill P's tail wave (independent work, one launch boundary saved).
__global__ void __launch_bounds__(128, 2)
gemm_vtp(const __half* __restrict__ Q, const __half* __restrict__ Kp, __half* __restrict__ P,
         const __half* __restrict__ wvT, const __half* __restrict__ x2h, __half* __restrict__ Vt)
{
    extern __shared__ char dsm[];
    const int z = blockIdx.z;
    if (z < BB) {
        gemm_core<true, false>(Q + (size_t)z * SS * DD, Kp + (size_t)z * SS * DD,
                               P + (size_t)z * SS * SS,
                               DD, DD, SS, DD / 16, 1.f,
                               blockIdx.y, blockIdx.x, dsm);
    } else {
        const int idx = blockIdx.x + (blockIdx.y << 4) + ((z - BB) << 8); // 0..1023
        gemm_core<true, false>(wvT, x2h, Vt,
                               DD, DD, MTOT, DD / 16, 1.f,
                               idx >> 7, idx & 127, dsm);
    }
}

// PV: per batch z, Y_z = h(relu(P_z @ Vt_z^T)).
__global__ void __launch_bounds__(128, 2)
gemm_pv(const __half* __restrict__ P, const __half* __restrict__ Vt, __half* __restrict__ Y)
{
    extern __shared__ char dsm[];
    const int z = blockIdx.z;
    gemm_core<true, true>(P + (size_t)z * SS * SS, Vt + (size_t)z * SS,
                          Y + (size_t)z * SS * DD,
                          SS, MTOT, DD, SS / 16, 1.f,
                          blockIdx.y, blockIdx.x, dsm);
}

// Output projection (fp32 out).
__global__ void __launch_bounds__(128, 2)
gemm_out(const __half* __restrict__ Y, const __half* __restrict__ woT, float* __restrict__ out)
{
    extern __shared__ char dsm[];
    gemm_core<false, false>(Y, woT, out, DD, DD, DD, DD / 16, 1.f,
                            blockIdx.y, blockIdx.x, dsm);
}

// ---------------------------------------------------------------------------
// Fused prep: fp32->fp16 of x1,x2 (32768 blocks) + 4 weight transposes (4096).
// ---------------------------------------------------------------------------
#define F2H_BLKS (MTOT * DD / 4 / 256)      // 16384 per tensor
__global__ void __launch_bounds__(256)
prep_all(const float4* __restrict__ x1, __half2* __restrict__ d1,
         const float4* __restrict__ x2, __half2* __restrict__ d2,
         const float* __restrict__ w0, const float* __restrict__ w1,
         const float* __restrict__ w2, const float* __restrict__ w3,
         __half* __restrict__ t0, __half* __restrict__ t1,
         __half* __restrict__ t2, __half* __restrict__ t3)
{
    __shared__ float t[32][33];
    const int bid = blockIdx.x;
    if (bid < 2 * F2H_BLKS) {
        const bool second = bid >= F2H_BLKS;
        const int i = (second ? bid - F2H_BLKS : bid) * 256 + threadIdx.x;
        const float4 v = (second ? x2 : x1)[i];
        __half2* d = second ? d2 : d1;
        d[2 * i]     = __floats2half2_rn(v.x, v.y);
        d[2 * i + 1] = __floats2half2_rn(v.z, v.w);
    } else {
        const int b2 = bid - 2 * F2H_BLKS;           // 0..4095
        const int wsel = b2 >> 10;
        const int tile = b2 & 1023;
        const int bx = (tile & 31) * 32, by = (tile >> 5) * 32;
        const float* w = (wsel == 0) ? w0 : (wsel == 1) ? w1 : (wsel == 2) ? w2 : w3;
        __half* wt     = (wsel == 0) ? t0 : (wsel == 1) ? t1 : (wsel == 2) ? t2 : t3;
        const int x = threadIdx.x & 31, y4 = threadIdx.x >> 5;
#pragma unroll
        for (int i = 0; i < 32; i += 8)
            t[y4 + i][x] = w[(size_t)(by + y4 + i) * DD + bx + x];
        __syncthreads();
#pragma unroll
        for (int i = 0; i < 32; i += 8)
            wt[(size_t)(bx + y4 + i) * DD + by + x] = __float2half_rn(t[x][y4 + i]);
    }
}

// ---------------------------------------------------------------------------
// Warp-per-row softmax with additive mask on fp16 P (R16 version).
// ---------------------------------------------------------------------------
__global__ void __launch_bounds__(256)
softmax_mask(__half* __restrict__ P, const int* __restrict__ mask)
{
    const int row  = blockIdx.x * 8 + (threadIdx.x >> 5);
    const int lane = threadIdx.x & 31;
    const int b    = row >> 11;
    int4* prow = (int4*)(P + (size_t)row * SS);
    const int4* mrow = (const int4*)(mask + (size_t)b * SS);

    float v[64];
    float mx = -INFINITY;
#pragma unroll
    for (int i = 0; i < 8; i++) {
        const int c = lane + i * 32;
        int4 pk = prow[c];
        const int4 m0 = mrow[2 * c];
        const int4 m1 = mrow[2 * c + 1];
        const int mAll[8] = { m0.x, m0.y, m0.z, m0.w, m1.x, m1.y, m1.z, m1.w };
        const __half2* h = (const __half2*)&pk;
#pragma unroll
        for (int j = 0; j < 4; j++) {
            float2 f = __half22float2(h[j]);
            if (mAll[2 * j])     f.x -= 1.0e9f;
            if (mAll[2 * j + 1]) f.y -= 1.0e9f;
            v[i * 8 + 2 * j]     = f.x;
            v[i * 8 + 2 * j + 1] = f.y;
            mx = fmaxf(mx, fmaxf(f.x, f.y));
        }
    }
#pragma unroll
    for (int o = 16; o; o >>= 1) mx = fmaxf(mx, __shfl_xor_sync(0xffffffffu, mx, o));

    float s = 0.f;
#pragma unroll
    for (int i = 0; i < 64; i++) {
        const float e = __expf(v[i] - mx);
        v[i] = e;
        s += e;
    }
#pragma unroll
    for (int o = 16; o; o >>= 1) s += __shfl_xor_sync(0xffffffffu, s, o);

    const float inv = 1.0f / s;
#pragma unroll
    for (int i = 0; i < 8; i++) {
        int4 pk;
        __half2* h = (__half2*)&pk;
#pragma unroll
        for (int j = 0; j < 4; j++)
            h[j] = __floats2half2_rn(v[i * 8 + 2 * j] * inv, v[i * 8 + 2 * j + 1] * inv);
        prow[lane + i * 32] = pk;
    }
}

// ---------------------------------------------------------------------------
// Launch
// ---------------------------------------------------------------------------
extern "C" void kernel_launch(void* const* d_in, const int* in_sizes, int n_in,
                              void* d_out, int out_size)
{
    (void)in_sizes; (void)n_in; (void)out_size;

    const float* x1      = (const float*)d_in[0];
    const float* x2      = (const float*)d_in[1];
    const int*   maskSeq = (const int*)  d_in[2];
    const float* wq      = (const float*)d_in[3];
    const float* wk      = (const float*)d_in[4];
    const float* wv      = (const float*)d_in[5];
    const float* wo      = (const float*)d_in[6];
    float* out = (float*)d_out;

    __half *x1h, *x2h, *wqT, *wkT, *wvT, *woT, *Q, *Kp, *Vt, *P, *Y;
    cudaGetSymbolAddress((void**)&x1h, g_x1h);
    cudaGetSymbolAddress((void**)&x2h, g_x2h);
    cudaGetSymbolAddress((void**)&wqT, g_wqT);
    cudaGetSymbolAddress((void**)&wkT, g_wkT);
    cudaGetSymbolAddress((void**)&wvT, g_wvT);
    cudaGetSymbolAddress((void**)&woT, g_woT);
    cudaGetSymbolAddress((void**)&Q,   g_Q);
    cudaGetSymbolAddress((void**)&Kp,  g_K);
    cudaGetSymbolAddress((void**)&Vt,  g_Vt);
    cudaGetSymbolAddress((void**)&P,   g_P);
    cudaGetSymbolAddress((void**)&Y,   g_Y);

    cudaFuncSetAttribute(gemm_qk,  cudaFuncAttributeMaxDynamicSharedMemorySize, SMEM_DYN);
    cudaFuncSetAttribute(gemm_vtp, cudaFuncAttributeMaxDynamicSharedMemorySize, SMEM_DYN);
    cudaFuncSetAttribute(gemm_pv,  cudaFuncAttributeMaxDynamicSharedMemorySize, SMEM_DYN);
    cudaFuncSetAttribute(gemm_out, cudaFuncAttributeMaxDynamicSharedMemorySize, SMEM_DYN);

    const float scale = 0.03125f;   // 1024^-0.5

    // fused prep: f2h(x1,x2) + 4 weight transposes
    prep_all<<<2 * F2H_BLKS + 4096, 256>>>(
        (const float4*)x1, (__half2*)x1h, (const float4*)x2, (__half2*)x2h,
        wq, wk, wv, wo, wqT, wkT, wvT, woT);

    // Q and K projections (merged, z=2)
    gemm_qk<<<dim3(DD / 128, MTOT / 128, 2), 128, SMEM_DYN>>>(
        x1h, wqT, Q, x2h, wkT, Kp, scale);

    // merged: P_z = Q_z @ K_z^T (z=0..7)  +  Vt = wvT @ x2h^T (z=8..11)
    gemm_vtp<<<dim3(16, 16, 12), 128, SMEM_DYN>>>(Q, Kp, P, wvT, x2h, Vt);

    // mask + softmax (in place, fp16; warp per row)
    softmax_mask<<<(BB * SS) / 8, 256>>>(P, maskSeq);

    // Y = h(relu(P @ Vt^T)) per batch
    gemm_pv<<<dim3(DD / 128, SS / 128, BB), 128, SMEM_DYN>>>(P, Vt, Y);

    // out = Y @ wo (fp32)
    gemm_out<<<dim3(DD / 128, MTOT / 128, 1), 128, SMEM_DYN>>>(Y, woT, out);
}